// round 1
// baseline (speedup 1.0000x reference)
#include <cuda_runtime.h>
#include <cstdint>

#define Bv 256
#define Tv 150
#define Fv 1024
#define Uv 28
#define G3 84   // 3*U

#define LOG2E  1.4426950408889634f
#define L2E2   2.8853900817779268f   // 2*log2(e)

// ---------------- scratch (device globals; no allocation allowed) ----------
__device__ float g_C[(size_t)Bv * Tv * Fv];   // pre-scaled UaH + biases  (157 MB)
__device__ float g_XG[(size_t)Bv * Tv * G3];  // x @ gru_kernel           (12.9 MB)
__device__ float g_WaS[Bv * Fv];              // pre-scaled h@Wa          (1 MB)
__device__ float g_scores[Bv * Tv];
__device__ float g_h[Bv * Uv];

// ---------------- fast-math helpers ----------------------------------------
__device__ __forceinline__ float ex2f(float x) {
    float y; asm("ex2.approx.ftz.f32 %0, %1;" : "=f"(y) : "f"(x)); return y;
}
__device__ __forceinline__ float rcpf(float x) {
    float y; asm("rcp.approx.ftz.f32 %0, %1;" : "=f"(y) : "f"(x)); return y;
}
// u is already 2*log2e * arg : tanh(arg) = 1 - 2/(exp(2 arg)+1)
__device__ __forceinline__ float tanh_pre(float u) {
    float e = ex2f(u);
    return fmaf(-2.0f, rcpf(e + 1.0f), 1.0f);
}
__device__ __forceinline__ float tanh_fast(float a) { return tanh_pre(a * L2E2); }
__device__ __forceinline__ float sigmoid_fast(float a) {
    float e = ex2f(-a * LOG2E);
    return rcpf(1.0f + e);
}

// ---------------- init ------------------------------------------------------
__global__ void init_kernel() {
    int i = blockIdx.x * blockDim.x + threadIdx.x;
    if (i < Bv * Fv) g_WaS[i] = 0.0f;
    if (i < Bv * Uv) g_h[i] = 0.0f;
}

// ---------------- 128x128x8 fp32 GEMM (row-major A[M,K] * B[K,N]) ----------
// C[m,n] = scale * ( sum_k A[m,k]B[k,n] + bias1[n] + bias2[n] )
// M multiple of 128, K == 1024. N guarded (N multiple of 4).
__global__ __launch_bounds__(256, 2)
void gemm128(const float* __restrict__ A, int lda,
             const float* __restrict__ Bm, int ldb,
             float* __restrict__ Cm, int ldc, int Ncols,
             const float* __restrict__ bias1,
             const float* __restrict__ bias2,
             float scale)
{
    __shared__ float As[8][132];
    __shared__ float Bs[8][128];

    int tid = threadIdx.x;
    int tx = tid & 15, ty = tid >> 4;
    int bm = blockIdx.y * 128;
    int bn = blockIdx.x * 128;

    int am = tid >> 1, ak = (tid & 1) * 4;
    int bk = tid >> 5, bcol = (tid & 31) * 4;
    bool bvalid = (bn + bcol) < Ncols;

    const float* Aptr = A + (size_t)(bm + am) * lda + ak;
    const float* Bptr = Bm + (size_t)bk * ldb + bn + bcol;

    float acc[8][8];
#pragma unroll
    for (int i = 0; i < 8; i++)
#pragma unroll
        for (int j = 0; j < 8; j++) acc[i][j] = 0.0f;

    for (int kt = 0; kt < Fv / 8; kt++) {
        float4 av = *(const float4*)(Aptr); Aptr += 8;
        float4 bv = make_float4(0.f, 0.f, 0.f, 0.f);
        if (bvalid) bv = *(const float4*)(Bptr);
        Bptr += 8 * (size_t)ldb;

        As[ak + 0][am] = av.x; As[ak + 1][am] = av.y;
        As[ak + 2][am] = av.z; As[ak + 3][am] = av.w;
        *(float4*)&Bs[bk][bcol] = bv;
        __syncthreads();

#pragma unroll
        for (int k = 0; k < 8; k++) {
            float4 a0 = *(const float4*)&As[k][ty * 8];
            float4 a1 = *(const float4*)&As[k][ty * 8 + 4];
            float4 b0 = *(const float4*)&Bs[k][tx * 8];
            float4 b1 = *(const float4*)&Bs[k][tx * 8 + 4];
            float ar[8] = {a0.x, a0.y, a0.z, a0.w, a1.x, a1.y, a1.z, a1.w};
            float br[8] = {b0.x, b0.y, b0.z, b0.w, b1.x, b1.y, b1.z, b1.w};
#pragma unroll
            for (int i = 0; i < 8; i++)
#pragma unroll
                for (int j = 0; j < 8; j++)
                    acc[i][j] = fmaf(ar[i], br[j], acc[i][j]);
        }
        __syncthreads();
    }

#pragma unroll
    for (int i = 0; i < 8; i++) {
        int row = bm + ty * 8 + i;
#pragma unroll
        for (int j4 = 0; j4 < 8; j4 += 4) {
            int col = bn + tx * 8 + j4;
            if (col < Ncols) {
                float4 o;
                float b0 = bias1 ? (bias1[col + 0] + bias2[col + 0]) : 0.f;
                float b1 = bias1 ? (bias1[col + 1] + bias2[col + 1]) : 0.f;
                float b2 = bias1 ? (bias1[col + 2] + bias2[col + 2]) : 0.f;
                float b3 = bias1 ? (bias1[col + 3] + bias2[col + 3]) : 0.f;
                o.x = scale * (acc[i][j4 + 0] + b0);
                o.y = scale * (acc[i][j4 + 1] + b1);
                o.z = scale * (acc[i][j4 + 2] + b2);
                o.w = scale * (acc[i][j4 + 3] + b3);
                *(float4*)&Cm[(size_t)row * ldc + col] = o;
            }
        }
    }
}

// ---------------- per-step score kernel ------------------------------------
// warp per (b,t) row: score = sum_f tanh(C'+WaS') * Va   (Ba3 dropped: softmax-invariant)
__global__ __launch_bounds__(256)
void score_kernel(const float* __restrict__ Va)
{
    int warp = threadIdx.x >> 5, lane = threadIdx.x & 31;
    int row = blockIdx.x * 8 + warp;          // < B*T = 38400
    int b = row / Tv;

    const float4* C4 = (const float4*)(g_C + (size_t)row * Fv);
    const float4* W4 = (const float4*)(g_WaS + (size_t)b * Fv);
    const float4* V4 = (const float4*)Va;

    float sum = 0.0f;
#pragma unroll
    for (int i = 0; i < 8; i++) {
        int idx = i * 32 + lane;
        float4 c = C4[idx];
        float4 w = W4[idx];
        float4 v = V4[idx];
        sum += tanh_pre(c.x + w.x) * v.x;
        sum += tanh_pre(c.y + w.y) * v.y;
        sum += tanh_pre(c.z + w.z) * v.z;
        sum += tanh_pre(c.w + w.w) * v.w;
    }
#pragma unroll
    for (int off = 16; off > 0; off >>= 1)
        sum += __shfl_xor_sync(0xffffffffu, sum, off);
    if (lane == 0) g_scores[row] = sum;
}

// ---------------- per-step softmax + GRU + next WaS (1 block per batch b) --
__global__ __launch_bounds__(256)
void att_gru_kernel(const float* __restrict__ Wa,
                    const float* __restrict__ grk,
                    const float* __restrict__ gb,
                    float* __restrict__ out, int tstep)
{
    int b = blockIdx.x, tid = threadIdx.x;

    __shared__ float sa[Tv];
    __shared__ float red[256];
    __shared__ float spart[3 * G3];
    __shared__ float sxz[G3], shz[G3];
    __shared__ float sh[Uv], shnew[Uv];

    if (tid < Uv) sh[tid] = g_h[b * Uv + tid];

    // ---- softmax over T=150 scores ----
    float v = (tid < Tv) ? g_scores[b * Tv + tid] : -1e30f;
    red[tid] = v;
    __syncthreads();
#pragma unroll
    for (int s = 128; s > 0; s >>= 1) {
        if (tid < s) red[tid] = fmaxf(red[tid], red[tid + s]);
        __syncthreads();
    }
    float mx = red[0];
    __syncthreads();
    float e = 0.0f;
    if (tid < Tv) e = ex2f((v - mx) * LOG2E);
    red[tid] = e;
    __syncthreads();
#pragma unroll
    for (int s = 128; s > 0; s >>= 1) {
        if (tid < s) red[tid] += red[tid + s];
        __syncthreads();
    }
    float inv = rcpf(red[0]);
    if (tid < Tv) sa[tid] = e * inv;
    __syncthreads();

    // ---- xz[j] = bias0[j] + sum_t a[t] * XG[b,t,j]  (ctx never materialized)
    int part = tid / G3;        // 0..2 used, part 3 (tid>=252) idle
    int j = tid - part * G3;
    if (part < 3) {
        float acc = 0.0f;
        const float* XGb = g_XG + (size_t)b * Tv * G3 + j;
        for (int t = part; t < Tv; t += 3)
            acc = fmaf(sa[t], XGb[t * G3], acc);
        spart[part * G3 + j] = acc;
    }
    __syncthreads();

    if (tid < G3) {
        float xz = gb[tid] + spart[tid] + spart[G3 + tid] + spart[2 * G3 + tid];
        float hzv = gb[G3 + tid];
#pragma unroll
        for (int u = 0; u < Uv; u++)
            hzv = fmaf(sh[u], grk[u * G3 + tid], hzv);
        sxz[tid] = xz;
        shz[tid] = hzv;
    }
    __syncthreads();

    // ---- GRU gates (reset_after=True) ----
    if (tid < Uv) {
        float z  = sigmoid_fast(sxz[tid]          + shz[tid]);
        float r  = sigmoid_fast(sxz[Uv + tid]     + shz[Uv + tid]);
        float hh = tanh_fast   (sxz[2 * Uv + tid] + r * shz[2 * Uv + tid]);
        float hn = hh + z * (sh[tid] - hh);
        g_h[b * Uv + tid] = hn;
        out[((size_t)b * Tv + tstep) * Uv + tid] = hn;
        shnew[tid] = hn;
    }
    __syncthreads();

    // ---- WaS' for next step: 2log2e * (h_new @ Wa) ----
    float4 w = make_float4(0.f, 0.f, 0.f, 0.f);
    const float4* Wa4 = (const float4*)Wa;
#pragma unroll
    for (int u = 0; u < Uv; u++) {
        float hv = shnew[u];
        float4 wv = Wa4[u * (Fv / 4) + tid];
        w.x = fmaf(hv, wv.x, w.x);
        w.y = fmaf(hv, wv.y, w.y);
        w.z = fmaf(hv, wv.z, w.z);
        w.w = fmaf(hv, wv.w, w.w);
    }
    w.x *= L2E2; w.y *= L2E2; w.z *= L2E2; w.w *= L2E2;
    ((float4*)g_WaS)[b * (Fv / 4) + tid] = w;
}

// ---------------- launch -----------------------------------------------------
extern "C" void kernel_launch(void* const* d_in, const int* in_sizes, int n_in,
                              void* d_out, int out_size)
{
    const float* x   = (const float*)d_in[0];  // (B,T,F)
    const float* Wa  = (const float*)d_in[1];  // (U,F)
    const float* Ua  = (const float*)d_in[2];  // (F,F)
    const float* Va  = (const float*)d_in[3];  // (F,1)
    const float* Ba1 = (const float*)d_in[4];  // (1,F)
    const float* Ba2 = (const float*)d_in[5];  // (1,F)
    // d_in[6] = Ba3 : softmax-invariant, unused
    const float* gk  = (const float*)d_in[7];  // (F,3U)
    const float* grk = (const float*)d_in[8];  // (U,3U)
    const float* gb  = (const float*)d_in[9];  // (2,3U)
    float* out = (float*)d_out;                // (B,T,U)

    // zero h and WaS (h0 = 0  =>  WaS'(step0) = 0; Ba1 folded into C)
    init_kernel<<<(Bv * Fv + 255) / 256, 256>>>();

    // C' = 2log2e * (x @ Ua + Ba1 + Ba2)   : M=38400, N=1024, K=1024
    {
        float* Cm;  cudaGetSymbolAddress((void**)&Cm, g_C);
        gemm128<<<dim3(Fv / 128, (Bv * Tv) / 128), 256>>>(
            x, Fv, Ua, Fv, Cm, Fv, Fv, Ba1, Ba2, L2E2);
    }
    // XG = x @ gru_kernel                  : M=38400, N=84, K=1024
    {
        float* XGm; cudaGetSymbolAddress((void**)&XGm, g_XG);
        gemm128<<<dim3(1, (Bv * Tv) / 128), 256>>>(
            x, Fv, gk, G3, XGm, G3, G3, nullptr, nullptr, 1.0f);
    }

    for (int t = 0; t < Tv; t++) {
        score_kernel<<<(Bv * Tv) / 8, 256>>>(Va);
        att_gru_kernel<<<Bv, 256>>>(Wa, grk, gb, out, t);
    }
}

// round 2
// speedup vs baseline: 1.4010x; 1.4010x over previous
#include <cuda_runtime.h>
#include <cuda_fp16.h>
#include <cstdint>

#define Bv 256
#define Tv 150
#define Fv 1024
#define Uv 28
#define G3 84   // 3*U

#define LOG2E  1.4426950408889634f

// ---------------- scratch (device globals; no allocation allowed) ----------
__device__ __half g_C[(size_t)Bv * Tv * Fv];   // UaH + biases, fp16 (78.6 MB)
__device__ __half g_XG[(size_t)Bv * Tv * G3];  // x @ gru_kernel, fp16 (6.4 MB)
__device__ __half g_WaS[Bv * Fv];              // h@Wa, fp16 (0.5 MB)
__device__ float  g_scores[Bv * Tv];
__device__ float  g_h[Bv * Uv];

// ---------------- fast-math helpers ----------------------------------------
__device__ __forceinline__ float ex2f(float x) {
    float y; asm("ex2.approx.ftz.f32 %0, %1;" : "=f"(y) : "f"(x)); return y;
}
__device__ __forceinline__ float rcpf(float x) {
    float y; asm("rcp.approx.ftz.f32 %0, %1;" : "=f"(y) : "f"(x)); return y;
}
__device__ __forceinline__ float tanh_hw(float x) {
    float y; asm("tanh.approx.f32 %0, %1;" : "=f"(y) : "f"(x)); return y;
}
// accurate-enough tanh for the GRU gates (tiny op count, keep precision)
__device__ __forceinline__ float tanh_acc(float a) {
    float e = ex2f(a * (2.0f * LOG2E));
    return fmaf(-2.0f, rcpf(e + 1.0f), 1.0f);
}
__device__ __forceinline__ float sigmoid_fast(float a) {
    float e = ex2f(-a * LOG2E);
    return rcpf(1.0f + e);
}

// ---------------- init ------------------------------------------------------
__global__ void init_kernel() {
    int i = blockIdx.x * blockDim.x + threadIdx.x;
    if (i < Bv * Fv) g_WaS[i] = __float2half(0.0f);
    if (i < Bv * Uv) g_h[i] = 0.0f;
}

// ---------------- 128x128x8 fp32 GEMM, fp16 output --------------------------
// C[m,n] = (half)( sum_k A[m,k]B[k,n] + bias1[n] + bias2[n] )
// M multiple of 128, K == 1024, Ncols guarded (multiple of 4).
__global__ __launch_bounds__(256, 2)
void gemm128h(const float* __restrict__ A, int lda,
              const float* __restrict__ Bm, int ldb,
              __half* __restrict__ Cm, int ldc, int Ncols,
              const float* __restrict__ bias1,
              const float* __restrict__ bias2)
{
    __shared__ float As[8][132];
    __shared__ float Bs[8][128];

    int tid = threadIdx.x;
    int tx = tid & 15, ty = tid >> 4;
    int bm = blockIdx.y * 128;
    int bn = blockIdx.x * 128;

    int am = tid >> 1, ak = (tid & 1) * 4;
    int bk = tid >> 5, bcol = (tid & 31) * 4;
    bool bvalid = (bn + bcol) < Ncols;

    const float* Aptr = A + (size_t)(bm + am) * lda + ak;
    const float* Bptr = Bm + (size_t)bk * ldb + bn + bcol;

    float acc[8][8];
#pragma unroll
    for (int i = 0; i < 8; i++)
#pragma unroll
        for (int j = 0; j < 8; j++) acc[i][j] = 0.0f;

    for (int kt = 0; kt < Fv / 8; kt++) {
        float4 av = *(const float4*)(Aptr); Aptr += 8;
        float4 bv = make_float4(0.f, 0.f, 0.f, 0.f);
        if (bvalid) bv = *(const float4*)(Bptr);
        Bptr += 8 * (size_t)ldb;

        As[ak + 0][am] = av.x; As[ak + 1][am] = av.y;
        As[ak + 2][am] = av.z; As[ak + 3][am] = av.w;
        *(float4*)&Bs[bk][bcol] = bv;
        __syncthreads();

#pragma unroll
        for (int k = 0; k < 8; k++) {
            float4 a0 = *(const float4*)&As[k][ty * 8];
            float4 a1 = *(const float4*)&As[k][ty * 8 + 4];
            float4 b0 = *(const float4*)&Bs[k][tx * 8];
            float4 b1 = *(const float4*)&Bs[k][tx * 8 + 4];
            float ar[8] = {a0.x, a0.y, a0.z, a0.w, a1.x, a1.y, a1.z, a1.w};
            float br[8] = {b0.x, b0.y, b0.z, b0.w, b1.x, b1.y, b1.z, b1.w};
#pragma unroll
            for (int i = 0; i < 8; i++)
#pragma unroll
                for (int j = 0; j < 8; j++)
                    acc[i][j] = fmaf(ar[i], br[j], acc[i][j]);
        }
        __syncthreads();
    }

#pragma unroll
    for (int i = 0; i < 8; i++) {
        int row = bm + ty * 8 + i;
#pragma unroll
        for (int j4 = 0; j4 < 8; j4 += 4) {
            int col = bn + tx * 8 + j4;
            if (col < Ncols) {
                float b0 = bias1 ? (bias1[col + 0] + bias2[col + 0]) : 0.f;
                float b1 = bias1 ? (bias1[col + 1] + bias2[col + 1]) : 0.f;
                float b2 = bias1 ? (bias1[col + 2] + bias2[col + 2]) : 0.f;
                float b3 = bias1 ? (bias1[col + 3] + bias2[col + 3]) : 0.f;
                __half2 p0 = __floats2half2_rn(acc[i][j4 + 0] + b0, acc[i][j4 + 1] + b1);
                __half2 p1 = __floats2half2_rn(acc[i][j4 + 2] + b2, acc[i][j4 + 3] + b3);
                uint2 pk;
                pk.x = *(uint32_t*)&p0;
                pk.y = *(uint32_t*)&p1;
                *(uint2*)&Cm[(size_t)row * ldc + col] = pk;
            }
        }
    }
}

// ---------------- per-step score kernel ------------------------------------
// warp per (b,t): score = sum_f tanh(C + WaS) * Va    (Ba3 softmax-invariant)
__global__ __launch_bounds__(256)
void score_kernel(const float* __restrict__ Va)
{
    int warp = threadIdx.x >> 5, lane = threadIdx.x & 31;
    int row = blockIdx.x * 8 + warp;          // < B*T = 38400
    int b = row / Tv;

    const uint4* C4 = (const uint4*)(g_C + (size_t)row * Fv);   // 8 halves each
    const uint4* W4 = (const uint4*)(g_WaS + (size_t)b * Fv);
    const float4* V4 = (const float4*)Va;

    float sum = 0.0f;
#pragma unroll
    for (int i = 0; i < 4; i++) {
        int idx = i * 32 + lane;              // 128 uint4 per row
        uint4 c = C4[idx];
        uint4 w = W4[idx];
        float4 va = V4[2 * idx];
        float4 vb = V4[2 * idx + 1];

        const __half2* ch = (const __half2*)&c;
        const __half2* wh = (const __half2*)&w;
#pragma unroll
        for (int k = 0; k < 4; k++) {
            float2 cf = __half22float2(ch[k]);
            float2 wf = __half22float2(wh[k]);
            float v0 = (k < 2) ? ((k == 0) ? va.x : va.z) : ((k == 2) ? vb.x : vb.z);
            float v1 = (k < 2) ? ((k == 0) ? va.y : va.w) : ((k == 2) ? vb.y : vb.w);
            sum = fmaf(tanh_hw(cf.x + wf.x), v0, sum);
            sum = fmaf(tanh_hw(cf.y + wf.y), v1, sum);
        }
    }
#pragma unroll
    for (int off = 16; off > 0; off >>= 1)
        sum += __shfl_xor_sync(0xffffffffu, sum, off);
    if (lane == 0) g_scores[row] = sum;
}

// ---------------- per-step softmax + GRU + next WaS (1 block per batch b) --
__global__ __launch_bounds__(256)
void att_gru_kernel(const float* __restrict__ Wa,
                    const float* __restrict__ grk,
                    const float* __restrict__ gb,
                    float* __restrict__ out, int tstep)
{
    int b = blockIdx.x, tid = threadIdx.x;

    __shared__ float sa[Tv];
    __shared__ float red[256];
    __shared__ float spart[3 * G3];
    __shared__ float sxz[G3], shz[G3];
    __shared__ float sh[Uv], shnew[Uv];

    if (tid < Uv) sh[tid] = g_h[b * Uv + tid];

    // ---- softmax over T=150 scores ----
    float v = (tid < Tv) ? g_scores[b * Tv + tid] : -1e30f;
    red[tid] = v;
    __syncthreads();
#pragma unroll
    for (int s = 128; s > 0; s >>= 1) {
        if (tid < s) red[tid] = fmaxf(red[tid], red[tid + s]);
        __syncthreads();
    }
    float mx = red[0];
    __syncthreads();
    float e = 0.0f;
    if (tid < Tv) e = ex2f((v - mx) * LOG2E);
    red[tid] = e;
    __syncthreads();
#pragma unroll
    for (int s = 128; s > 0; s >>= 1) {
        if (tid < s) red[tid] += red[tid + s];
        __syncthreads();
    }
    float inv = rcpf(red[0]);
    if (tid < Tv) sa[tid] = e * inv;
    __syncthreads();

    // ---- xz[j] = bias0[j] + sum_t a[t] * XG[b,t,j]  (ctx never materialized)
    int part = tid / G3;        // 0..2 used; tid>=252 idle
    int j = tid - part * G3;
    if (part < 3) {
        float acc = 0.0f;
        const __half* XGb = g_XG + (size_t)b * Tv * G3 + j;
        for (int t = part; t < Tv; t += 3)
            acc = fmaf(sa[t], __half2float(XGb[t * G3]), acc);
        spart[part * G3 + j] = acc;
    }
    __syncthreads();

    if (tid < G3) {
        float xz = gb[tid] + spart[tid] + spart[G3 + tid] + spart[2 * G3 + tid];
        float hzv = gb[G3 + tid];
#pragma unroll
        for (int u = 0; u < Uv; u++)
            hzv = fmaf(sh[u], grk[u * G3 + tid], hzv);
        sxz[tid] = xz;
        shz[tid] = hzv;
    }
    __syncthreads();

    // ---- GRU gates (reset_after=True) ----
    if (tid < Uv) {
        float z  = sigmoid_fast(sxz[tid]          + shz[tid]);
        float r  = sigmoid_fast(sxz[Uv + tid]     + shz[Uv + tid]);
        float hh = tanh_acc    (sxz[2 * Uv + tid] + r * shz[2 * Uv + tid]);
        float hn = hh + z * (sh[tid] - hh);
        g_h[b * Uv + tid] = hn;
        out[((size_t)b * Tv + tstep) * Uv + tid] = hn;
        shnew[tid] = hn;
    }
    __syncthreads();

    // ---- WaS for next step: h_new @ Wa  (stored fp16) ----
    float4 w = make_float4(0.f, 0.f, 0.f, 0.f);
    const float4* Wa4 = (const float4*)Wa;
#pragma unroll
    for (int u = 0; u < Uv; u++) {
        float hv = shnew[u];
        float4 wv = Wa4[u * (Fv / 4) + tid];
        w.x = fmaf(hv, wv.x, w.x);
        w.y = fmaf(hv, wv.y, w.y);
        w.z = fmaf(hv, wv.z, w.z);
        w.w = fmaf(hv, wv.w, w.w);
    }
    __half2 p0 = __floats2half2_rn(w.x, w.y);
    __half2 p1 = __floats2half2_rn(w.z, w.w);
    uint2 pk;
    pk.x = *(uint32_t*)&p0;
    pk.y = *(uint32_t*)&p1;
    ((uint2*)g_WaS)[b * (Fv / 4) + tid] = pk;
}

// ---------------- launch -----------------------------------------------------
extern "C" void kernel_launch(void* const* d_in, const int* in_sizes, int n_in,
                              void* d_out, int out_size)
{
    const float* x   = (const float*)d_in[0];  // (B,T,F)
    const float* Wa  = (const float*)d_in[1];  // (U,F)
    const float* Ua  = (const float*)d_in[2];  // (F,F)
    const float* Va  = (const float*)d_in[3];  // (F,1)
    const float* Ba1 = (const float*)d_in[4];  // (1,F)
    const float* Ba2 = (const float*)d_in[5];  // (1,F)
    // d_in[6] = Ba3 : softmax-invariant, unused
    const float* gk  = (const float*)d_in[7];  // (F,3U)
    const float* grk = (const float*)d_in[8];  // (U,3U)
    const float* gb  = (const float*)d_in[9];  // (2,3U)
    float* out = (float*)d_out;                // (B,T,U)

    init_kernel<<<(Bv * Fv + 255) / 256, 256>>>();

    __half* Cm;  cudaGetSymbolAddress((void**)&Cm, g_C);
    __half* XGm; cudaGetSymbolAddress((void**)&XGm, g_XG);

    // C = x @ Ua + Ba1 + Ba2  : M=38400, N=1024, K=1024  (fp16 out)
    gemm128h<<<dim3(Fv / 128, (Bv * Tv) / 128), 256>>>(
        x, Fv, Ua, Fv, Cm, Fv, Fv, Ba1, Ba2);
    // XG = x @ gru_kernel     : M=38400, N=84, K=1024    (fp16 out)
    gemm128h<<<dim3(1, (Bv * Tv) / 128), 256>>>(
        x, Fv, gk, G3, XGm, G3, G3, nullptr, nullptr);

    for (int t = 0; t < Tv; t++) {
        score_kernel<<<(Bv * Tv) / 8, 256>>>(Va);
        att_gru_kernel<<<Bv, 256>>>(Wa, grk, gb, out, t);
    }
}

// round 3
// speedup vs baseline: 1.9659x; 1.4032x over previous
#include <cuda_runtime.h>
#include <cuda_fp16.h>
#include <cstdint>

#define Bv 256
#define Tv 150
#define Fv 1024
#define Uv 28
#define G3 84   // 3*U

#define LOG2E  1.4426950408889634f

// ---------------- scratch (device globals; no allocation allowed) ----------
__device__ __half g_C[(size_t)Bv * Tv * Fv];   // UaH + biases, fp16 (78.6 MB)
__device__ __half g_XG[(size_t)Bv * Tv * G3];  // x @ gru_kernel, fp16 (6.4 MB)
__device__ __half g_WaS[Bv * Fv];              // h@Wa, fp16 (0.5 MB)
__device__ float  g_scores[Bv * Tv];
__device__ float  g_h[Bv * Uv];

// ---------------- fast-math helpers ----------------------------------------
__device__ __forceinline__ float ex2f(float x) {
    float y; asm("ex2.approx.ftz.f32 %0, %1;" : "=f"(y) : "f"(x)); return y;
}
__device__ __forceinline__ float rcpf(float x) {
    float y; asm("rcp.approx.ftz.f32 %0, %1;" : "=f"(y) : "f"(x)); return y;
}
__device__ __forceinline__ float tanh_hw(float x) {
    float y; asm("tanh.approx.f32 %0, %1;" : "=f"(y) : "f"(x)); return y;
}
__device__ __forceinline__ float tanh_acc(float a) {
    float e = ex2f(a * (2.0f * LOG2E));
    return fmaf(-2.0f, rcpf(e + 1.0f), 1.0f);
}
__device__ __forceinline__ float sigmoid_fast(float a) {
    float e = ex2f(-a * LOG2E);
    return rcpf(1.0f + e);
}

// ---------------- init ------------------------------------------------------
__global__ void init_kernel() {
    int i = blockIdx.x * blockDim.x + threadIdx.x;
    if (i < Bv * Fv) g_WaS[i] = __float2half(0.0f);
    if (i < Bv * Uv) g_h[i] = 0.0f;
}

// ---------------- tensor-core GEMM: fp32 in (converted to fp16), fp32 acc --
// C[m,n] = (half)( sum_k A[m,k]*B[k,n] + bias1[n] + bias2[n] )
// A row-major [M,K], B row-major [K,N]. M mult of 128, K mult of 16.
#define BM 128
#define BN 128
#define BKg 16
#define PITCH 24   // halves; verified conflict-free fragment loads

__device__ __forceinline__ void mma16816(float* d,
    uint32_t a0, uint32_t a1, uint32_t a2, uint32_t a3,
    uint32_t b0, uint32_t b1)
{
    asm volatile(
        "mma.sync.aligned.m16n8k16.row.col.f32.f16.f16.f32 "
        "{%0,%1,%2,%3}, {%4,%5,%6,%7}, {%8,%9}, {%0,%1,%2,%3};"
        : "+f"(d[0]), "+f"(d[1]), "+f"(d[2]), "+f"(d[3])
        : "r"(a0), "r"(a1), "r"(a2), "r"(a3), "r"(b0), "r"(b1));
}

__global__ __launch_bounds__(256)
void gemm_mma(const float* __restrict__ A, int lda,
              const float* __restrict__ Bm, int ldb,
              __half* __restrict__ Cm, int ldc, int Ncols,
              const float* __restrict__ bias1,
              const float* __restrict__ bias2)
{
    __shared__ __align__(16) __half As[BM * PITCH];   // [m][k]
    __shared__ __align__(16) __half Bs[BN * PITCH];   // [n][k]

    int tid = threadIdx.x, lane = tid & 31, wid = tid >> 5;
    int warp_m = wid & 3, warp_n = wid >> 2;     // 4 x 2 warp grid
    int bm = blockIdx.y * BM, bn = blockIdx.x * BN;
    int g = lane >> 2, tg = lane & 3;

    // prefetch indices
    int a_row[2], a_kq[2], b_n[2], b_kq[2];
#pragma unroll
    for (int i = 0; i < 2; i++) {
        int fa = tid + 256 * i;
        a_row[i] = fa >> 2; a_kq[i] = fa & 3;
        b_n[i] = fa & 127;  b_kq[i] = fa >> 7;
    }

    float4 pa[2];
    float  pb[2][4];

    // ---- prefetch tile 0 ----
#pragma unroll
    for (int i = 0; i < 2; i++) {
        pa[i] = *(const float4*)&A[(size_t)(bm + a_row[i]) * lda + a_kq[i] * 4];
        int col = bn + b_n[i];
        bool ok = col < Ncols;
#pragma unroll
        for (int j = 0; j < 4; j++)
            pb[i][j] = ok ? Bm[(size_t)(b_kq[i] * 4 + j) * ldb + col] : 0.0f;
    }

    float acc[2][8][4];
#pragma unroll
    for (int t = 0; t < 2; t++)
#pragma unroll
        for (int j = 0; j < 8; j++)
#pragma unroll
            for (int q = 0; q < 4; q++) acc[t][j][q] = 0.0f;

    const int KT = Fv / BKg;   // 64
    for (int kt = 0; kt < KT; kt++) {
        __syncthreads();
        // store prefetched tile
#pragma unroll
        for (int i = 0; i < 2; i++) {
            __half2 h0 = __floats2half2_rn(pa[i].x, pa[i].y);
            __half2 h1 = __floats2half2_rn(pa[i].z, pa[i].w);
            *(__half2*)&As[a_row[i] * PITCH + a_kq[i] * 4]     = h0;
            *(__half2*)&As[a_row[i] * PITCH + a_kq[i] * 4 + 2] = h1;
            __half2 g0 = __floats2half2_rn(pb[i][0], pb[i][1]);
            __half2 g1 = __floats2half2_rn(pb[i][2], pb[i][3]);
            *(__half2*)&Bs[b_n[i] * PITCH + b_kq[i] * 4]     = g0;
            *(__half2*)&Bs[b_n[i] * PITCH + b_kq[i] * 4 + 2] = g1;
        }
        // prefetch next tile
        if (kt + 1 < KT) {
            int k0 = (kt + 1) * BKg;
#pragma unroll
            for (int i = 0; i < 2; i++) {
                pa[i] = *(const float4*)&A[(size_t)(bm + a_row[i]) * lda + k0 + a_kq[i] * 4];
                int col = bn + b_n[i];
                bool ok = col < Ncols;
#pragma unroll
                for (int j = 0; j < 4; j++)
                    pb[i][j] = ok ? Bm[(size_t)(k0 + b_kq[i] * 4 + j) * ldb + col] : 0.0f;
            }
        }
        __syncthreads();

        // fragments + mma
        uint32_t af[2][4];
#pragma unroll
        for (int t = 0; t < 2; t++) {
            int m = warp_m * 32 + t * 16 + g;
            af[t][0] = *(const uint32_t*)&As[m * PITCH + tg * 2];
            af[t][1] = *(const uint32_t*)&As[(m + 8) * PITCH + tg * 2];
            af[t][2] = *(const uint32_t*)&As[m * PITCH + tg * 2 + 8];
            af[t][3] = *(const uint32_t*)&As[(m + 8) * PITCH + tg * 2 + 8];
        }
#pragma unroll
        for (int j = 0; j < 8; j++) {
            int n = warp_n * 64 + j * 8 + g;
            uint32_t b0 = *(const uint32_t*)&Bs[n * PITCH + tg * 2];
            uint32_t b1 = *(const uint32_t*)&Bs[n * PITCH + tg * 2 + 8];
#pragma unroll
            for (int t = 0; t < 2; t++)
                mma16816(acc[t][j], af[t][0], af[t][1], af[t][2], af[t][3], b0, b1);
        }
    }

    // epilogue
#pragma unroll
    for (int t = 0; t < 2; t++) {
        int row = bm + warp_m * 32 + t * 16 + g;
#pragma unroll
        for (int j = 0; j < 8; j++) {
            int col = bn + warp_n * 64 + j * 8 + tg * 2;
            if (col < Ncols) {
                float bb0 = 0.f, bb1 = 0.f;
                if (bias1) {
                    bb0 = bias1[col] + bias2[col];
                    bb1 = bias1[col + 1] + bias2[col + 1];
                }
                __half2 lo = __floats2half2_rn(acc[t][j][0] + bb0, acc[t][j][1] + bb1);
                __half2 hi = __floats2half2_rn(acc[t][j][2] + bb0, acc[t][j][3] + bb1);
                *(__half2*)&Cm[(size_t)row * ldc + col]       = lo;
                *(__half2*)&Cm[(size_t)(row + 8) * ldc + col] = hi;
            }
        }
    }
}

// ---------------- per-step score kernel ------------------------------------
// warp per (b,t): score = sum_f tanh(C + WaS) * Va    (Ba3 softmax-invariant)
__global__ __launch_bounds__(256)
void score_kernel(const float* __restrict__ Va)
{
    int warp = threadIdx.x >> 5, lane = threadIdx.x & 31;
    int row = blockIdx.x * 8 + warp;          // < B*T = 38400
    int b = row / Tv;

    const uint4* C4 = (const uint4*)(g_C + (size_t)row * Fv);   // 8 halves each
    const uint4* W4 = (const uint4*)(g_WaS + (size_t)b * Fv);
    const float4* V4 = (const float4*)Va;

    float acc0 = 0.f, acc1 = 0.f, acc2 = 0.f, acc3 = 0.f;
#pragma unroll
    for (int i = 0; i < 4; i++) {
        int idx = i * 32 + lane;              // 128 uint4 per row
        uint4 c = C4[idx];
        uint4 w = W4[idx];
        float4 va = V4[2 * idx];
        float4 vb = V4[2 * idx + 1];
        const __half2* ch = (const __half2*)&c;
        const __half2* wh = (const __half2*)&w;

        float2 s0 = __half22float2(__hadd2(ch[0], wh[0]));
        float2 s1 = __half22float2(__hadd2(ch[1], wh[1]));
        float2 s2 = __half22float2(__hadd2(ch[2], wh[2]));
        float2 s3 = __half22float2(__hadd2(ch[3], wh[3]));

        acc0 = fmaf(tanh_hw(s0.x), va.x, acc0);
        acc1 = fmaf(tanh_hw(s0.y), va.y, acc1);
        acc2 = fmaf(tanh_hw(s1.x), va.z, acc2);
        acc3 = fmaf(tanh_hw(s1.y), va.w, acc3);
        acc0 = fmaf(tanh_hw(s2.x), vb.x, acc0);
        acc1 = fmaf(tanh_hw(s2.y), vb.y, acc1);
        acc2 = fmaf(tanh_hw(s3.x), vb.z, acc2);
        acc3 = fmaf(tanh_hw(s3.y), vb.w, acc3);
    }
    float sum = (acc0 + acc1) + (acc2 + acc3);
#pragma unroll
    for (int off = 16; off > 0; off >>= 1)
        sum += __shfl_xor_sync(0xffffffffu, sum, off);
    if (lane == 0) g_scores[row] = sum;
}

// ---------------- per-step softmax + GRU + next WaS (1 block per batch b) --
__global__ __launch_bounds__(256)
void att_gru_kernel(const float* __restrict__ Wa,
                    const float* __restrict__ grk,
                    const float* __restrict__ gb,
                    float* __restrict__ out, int tstep)
{
    int b = blockIdx.x, tid = threadIdx.x;

    __shared__ float sa[Tv];
    __shared__ float red[256];
    __shared__ float spart[3 * G3];
    __shared__ float sxz[G3], shz[G3];
    __shared__ float sh[Uv], shnew[Uv];

    if (tid < Uv) sh[tid] = g_h[b * Uv + tid];

    // ---- softmax over T=150 scores ----
    float v = (tid < Tv) ? g_scores[b * Tv + tid] : -1e30f;
    red[tid] = v;
    __syncthreads();
#pragma unroll
    for (int s = 128; s > 0; s >>= 1) {
        if (tid < s) red[tid] = fmaxf(red[tid], red[tid + s]);
        __syncthreads();
    }
    float mx = red[0];
    __syncthreads();
    float e = 0.0f;
    if (tid < Tv) e = ex2f((v - mx) * LOG2E);
    red[tid] = e;
    __syncthreads();
#pragma unroll
    for (int s = 128; s > 0; s >>= 1) {
        if (tid < s) red[tid] += red[tid + s];
        __syncthreads();
    }
    float inv = rcpf(red[0]);
    if (tid < Tv) sa[tid] = e * inv;
    __syncthreads();

    // ---- xz[j] = bias0[j] + sum_t a[t] * XG[b,t,j] ----
    int part = tid / G3;        // 0..2 used; tid>=252 idle
    int j = tid - part * G3;
    if (part < 3) {
        float acc = 0.0f;
        const __half* XGb = g_XG + (size_t)b * Tv * G3 + j;
        for (int t = part; t < Tv; t += 3)
            acc = fmaf(sa[t], __half2float(XGb[t * G3]), acc);
        spart[part * G3 + j] = acc;
    }
    __syncthreads();

    if (tid < G3) {
        float xz = gb[tid] + spart[tid] + spart[G3 + tid] + spart[2 * G3 + tid];
        float hzv = gb[G3 + tid];
#pragma unroll
        for (int u = 0; u < Uv; u++)
            hzv = fmaf(sh[u], grk[u * G3 + tid], hzv);
        sxz[tid] = xz;
        shz[tid] = hzv;
    }
    __syncthreads();

    // ---- GRU gates (reset_after=True) ----
    if (tid < Uv) {
        float z  = sigmoid_fast(sxz[tid]          + shz[tid]);
        float r  = sigmoid_fast(sxz[Uv + tid]     + shz[Uv + tid]);
        float hh = tanh_acc    (sxz[2 * Uv + tid] + r * shz[2 * Uv + tid]);
        float hn = hh + z * (sh[tid] - hh);
        g_h[b * Uv + tid] = hn;
        out[((size_t)b * Tv + tstep) * Uv + tid] = hn;
        shnew[tid] = hn;
    }
    __syncthreads();

    // ---- WaS for next step: h_new @ Wa (stored fp16) ----
    float4 w = make_float4(0.f, 0.f, 0.f, 0.f);
    const float4* Wa4 = (const float4*)Wa;
#pragma unroll
    for (int u = 0; u < Uv; u++) {
        float hv = shnew[u];
        float4 wv = Wa4[u * (Fv / 4) + tid];
        w.x = fmaf(hv, wv.x, w.x);
        w.y = fmaf(hv, wv.y, w.y);
        w.z = fmaf(hv, wv.z, w.z);
        w.w = fmaf(hv, wv.w, w.w);
    }
    __half2 p0 = __floats2half2_rn(w.x, w.y);
    __half2 p1 = __floats2half2_rn(w.z, w.w);
    uint2 pk;
    pk.x = *(uint32_t*)&p0;
    pk.y = *(uint32_t*)&p1;
    ((uint2*)g_WaS)[b * (Fv / 4) + tid] = pk;
}

// ---------------- launch -----------------------------------------------------
extern "C" void kernel_launch(void* const* d_in, const int* in_sizes, int n_in,
                              void* d_out, int out_size)
{
    const float* x   = (const float*)d_in[0];  // (B,T,F)
    const float* Wa  = (const float*)d_in[1];  // (U,F)
    const float* Ua  = (const float*)d_in[2];  // (F,F)
    const float* Va  = (const float*)d_in[3];  // (F,1)
    const float* Ba1 = (const float*)d_in[4];  // (1,F)
    const float* Ba2 = (const float*)d_in[5];  // (1,F)
    // d_in[6] = Ba3 : softmax-invariant, unused
    const float* gk  = (const float*)d_in[7];  // (F,3U)
    const float* grk = (const float*)d_in[8];  // (U,3U)
    const float* gb  = (const float*)d_in[9];  // (2,3U)
    float* out = (float*)d_out;                // (B,T,U)

    init_kernel<<<(Bv * Fv + 255) / 256, 256>>>();

    __half* Cm;  cudaGetSymbolAddress((void**)&Cm, g_C);
    __half* XGm; cudaGetSymbolAddress((void**)&XGm, g_XG);

    // C = x @ Ua + Ba1 + Ba2  : M=38400, N=1024, K=1024  (fp16 out, HMMA)
    gemm_mma<<<dim3(Fv / BN, (Bv * Tv) / BM), 256>>>(
        x, Fv, Ua, Fv, Cm, Fv, Fv, Ba1, Ba2);
    // XG = x @ gru_kernel     : M=38400, N=84, K=1024    (fp16 out, HMMA)
    gemm_mma<<<dim3(1, (Bv * Tv) / BM), 256>>>(
        x, Fv, gk, G3, XGm, G3, G3, nullptr, nullptr);

    for (int t = 0; t < Tv; t++) {
        score_kernel<<<(Bv * Tv) / 8, 256>>>(Va);
        att_gru_kernel<<<Bv, 256>>>(Wa, grk, gb, out, t);
    }
}